// round 2
// baseline (speedup 1.0000x reference)
#include <cuda_runtime.h>
#include <math.h>

// IAF, 2 MADE flows, B=4096, D=H=64.
// Identity (verified R1, rel_err 5e-8): the reference's forward scan is the exact
// inverse of z -> z - shift(z), so density depends only on z_logvar and eps:
//   density = -0.5*D*log(2pi) - 0.5*sum(lv) - 0.5*sum(eps^2)
// Remaining work: inverse pass = 8 masked [4096x64]@[64x64] GEMMs.
//
// R2 design: warp = 4 rows x 8 col-threads (8 outputs/thread). Activations and z
// stay in registers; x[d] broadcast via SHFL.IDX (reg index compile-time).
// Only weights live in smem (masked once per block). No mainloop barriers.

#define NT 256
#define RB 32

__device__ __forceinline__ void layer64(const float (&in)[8], float (&out)[8],
                                        const float* __restrict__ W,
                                        const float* __restrict__ bb,
                                        const int (&xs)[8], int j0, bool do_relu)
{
    float acc[8];
    float4 bA = *(const float4*)(bb + j0);
    float4 bB = *(const float4*)(bb + j0 + 4);
    acc[0] = bA.x; acc[1] = bA.y; acc[2] = bA.z; acc[3] = bA.w;
    acc[4] = bB.x; acc[5] = bB.y; acc[6] = bB.z; acc[7] = bB.w;
    #pragma unroll
    for (int d = 0; d < 64; ++d) {
        float xv = __shfl_sync(0xffffffffu, in[d & 7], xs[d >> 3]);
        float4 w0 = *(const float4*)(W + d * 64 + j0);
        float4 w1 = *(const float4*)(W + d * 64 + j0 + 4);
        acc[0] = fmaf(xv, w0.x, acc[0]);
        acc[1] = fmaf(xv, w0.y, acc[1]);
        acc[2] = fmaf(xv, w0.z, acc[2]);
        acc[3] = fmaf(xv, w0.w, acc[3]);
        acc[4] = fmaf(xv, w1.x, acc[4]);
        acc[5] = fmaf(xv, w1.y, acc[5]);
        acc[6] = fmaf(xv, w1.z, acc[6]);
        acc[7] = fmaf(xv, w1.w, acc[7]);
    }
    #pragma unroll
    for (int i = 0; i < 8; ++i)
        out[i] = do_relu ? fmaxf(acc[i], 0.0f) : acc[i];
}

__global__ __launch_bounds__(NT, 1)
void iaf_kernel(const float* __restrict__ zm, const float* __restrict__ lvp,
                const float* __restrict__ ep,
                const float* __restrict__ W0, const float* __restrict__ b0,
                const float* __restrict__ W1, const float* __restrict__ b1,
                const float* __restrict__ W2, const float* __restrict__ b2,
                const float* __restrict__ Wo, const float* __restrict__ bo,
                float* __restrict__ out, int B)
{
    extern __shared__ float sm[];
    float* wts = sm;               // 8 matrices * 4096 floats, [flow*4+layer][k][col]
    float* bss = wts + 8 * 4096;   // 8 * 64 biases

    const int tid = threadIdx.x;

    // ---- Preamble: mask-premultiplied weights into smem (float4 path).
    // d_h[h] = h % 63 + 1. Masks:
    //   m_in [d][h]: (d+1) <= d_h[h]  <=> d      <= (h%63)
    //   m_hid[k][j]: d_h[k] <= d_h[j] <=> (k%63) <= (j%63)
    //   m_out[h][d]: d_h[h] <  (d+1)  <=> (h%63) <  d
    for (int i = tid; i < 2048; i += NT) {       // 2048 float4 per matrix (2 flows)
        int idx = i << 2;                        // element index into [2,64,64]
        int f   = idx >> 12;
        int e   = idx & 4095;
        int row = e >> 6;
        int c0  = e & 63;                        // first of 4 consecutive cols
        int dhr = row % 63;
        float4 w0 = *(const float4*)(W0 + idx);
        float4 w1 = *(const float4*)(W1 + idx);
        float4 w2 = *(const float4*)(W2 + idx);
        float4 wo = *(const float4*)(Wo + idx);
        float4 o0, o1, o2, oo;
        {
            int c = c0,     dhc = c % 63;
            o0.x = (row <= dhc) ? w0.x : 0.f; o1.x = (dhr <= dhc) ? w1.x : 0.f;
            o2.x = (dhr <= dhc) ? w2.x : 0.f; oo.x = (dhr <  c)   ? wo.x : 0.f;
        }
        {
            int c = c0 + 1, dhc = c % 63;
            o0.y = (row <= dhc) ? w0.y : 0.f; o1.y = (dhr <= dhc) ? w1.y : 0.f;
            o2.y = (dhr <= dhc) ? w2.y : 0.f; oo.y = (dhr <  c)   ? wo.y : 0.f;
        }
        {
            int c = c0 + 2, dhc = c % 63;
            o0.z = (row <= dhc) ? w0.z : 0.f; o1.z = (dhr <= dhc) ? w1.z : 0.f;
            o2.z = (dhr <= dhc) ? w2.z : 0.f; oo.z = (dhr <  c)   ? wo.z : 0.f;
        }
        {
            int c = c0 + 3, dhc = c % 63;
            o0.w = (row <= dhc) ? w0.w : 0.f; o1.w = (dhr <= dhc) ? w1.w : 0.f;
            o2.w = (dhr <= dhc) ? w2.w : 0.f; oo.w = (dhr <  c)   ? wo.w : 0.f;
        }
        *(float4*)(wts + (f * 4 + 0) * 4096 + e) = o0;
        *(float4*)(wts + (f * 4 + 1) * 4096 + e) = o1;
        *(float4*)(wts + (f * 4 + 2) * 4096 + e) = o2;
        *(float4*)(wts + (f * 4 + 3) * 4096 + e) = oo;
    }
    for (int idx = tid; idx < 2 * 64; idx += NT) {
        int f = idx >> 6, j = idx & 63;
        bss[(f * 4 + 0) * 64 + j] = b0[idx];
        bss[(f * 4 + 1) * 64 + j] = b1[idx];
        bss[(f * 4 + 2) * 64 + j] = b2[idx];
        bss[(f * 4 + 3) * 64 + j] = bo[idx];
    }

    const int lane = tid & 31;
    const int warp = tid >> 5;
    const int ct   = lane & 7;          // col-thread within row (8 cols each)
    const int rloc = lane >> 3;         // row within warp (0..3)
    const int j0   = ct << 3;
    const int row  = blockIdx.x * RB + (warp << 2) + rloc;
    const bool valid = (row < B);

    // shfl source lanes: x[d] lives in lane (lane&0x18)|(d>>3), reg d&7
    int xs[8];
    {
        int base = lane & 0x18;
        #pragma unroll
        for (int k = 0; k < 8; ++k) xs[k] = base + k;
    }
    const int rev_src = (lane & 0x18) | (7 - ct);

    // ---- Init: z0 = zm + exp(0.5*lv)*eps ; density from lv, eps.
    float z[8];
    {
        float4 zmA = make_float4(0,0,0,0), zmB = zmA;
        float4 lvA = zmA, lvB = zmA, epA = zmA, epB = zmA;
        if (valid) {
            const size_t o = (size_t)row * 64 + j0;
            zmA = *(const float4*)(zm + o);  zmB = *(const float4*)(zm + o + 4);
            lvA = *(const float4*)(lvp + o); lvB = *(const float4*)(lvp + o + 4);
            epA = *(const float4*)(ep + o);  epB = *(const float4*)(ep + o + 4);
        }
        z[0] = zmA.x + expf(0.5f * lvA.x) * epA.x;
        z[1] = zmA.y + expf(0.5f * lvA.y) * epA.y;
        z[2] = zmA.z + expf(0.5f * lvA.z) * epA.z;
        z[3] = zmA.w + expf(0.5f * lvA.w) * epA.w;
        z[4] = zmB.x + expf(0.5f * lvB.x) * epB.x;
        z[5] = zmB.y + expf(0.5f * lvB.y) * epB.y;
        z[6] = zmB.z + expf(0.5f * lvB.z) * epB.z;
        z[7] = zmB.w + expf(0.5f * lvB.w) * epB.w;

        float slv = lvA.x + lvA.y + lvA.z + lvA.w + lvB.x + lvB.y + lvB.z + lvB.w;
        float se2 = epA.x*epA.x + epA.y*epA.y + epA.z*epA.z + epA.w*epA.w
                  + epB.x*epB.x + epB.y*epB.y + epB.z*epB.z + epB.w*epB.w;
        #pragma unroll
        for (int off = 4; off; off >>= 1) {
            slv += __shfl_xor_sync(0xffffffffu, slv, off);
            se2 += __shfl_xor_sync(0xffffffffu, se2, off);
        }
        if (ct == 0 && valid) {
            float dens = -0.5f * 64.0f * 1.8378770664093453f - 0.5f * slv - 0.5f * se2;
            out[(size_t)B * 64 + row] = dens;
        }
    }
    __syncthreads();   // weights ready

    // ---- Inverse pass: flow 1 then flow 0 (reverse between them). No barriers.
    float a[8], t[8];
    #pragma unroll 1
    for (int fi = 0; fi < 2; ++fi) {
        const int f = 1 - fi;
        const float* wb = wts + f * 4 * 4096;
        const float* bp = bss + f * 4 * 64;

        layer64(z, a, wb,            bp,       xs, j0, true);
        layer64(a, a, wb + 4096,     bp + 64,  xs, j0, true);
        layer64(a, a, wb + 2 * 4096, bp + 128, xs, j0, true);
        layer64(a, t, wb + 3 * 4096, bp + 192, xs, j0, false);

        #pragma unroll
        for (int i = 0; i < 8; ++i) z[i] -= t[i];

        if (fi == 0) {
            // z <- z[..., ::-1]: new z[8ct+i] = old z[8(7-ct)+(7-i)]
            float r[8];
            #pragma unroll
            for (int i = 0; i < 8; ++i)
                r[i] = __shfl_sync(0xffffffffu, z[7 - i], rev_src);
            #pragma unroll
            for (int i = 0; i < 8; ++i) z[i] = r[i];
        }
    }

    if (valid) {
        const size_t o = (size_t)row * 64 + j0;
        *(float4*)(out + o)     = make_float4(z[0], z[1], z[2], z[3]);
        *(float4*)(out + o + 4) = make_float4(z[4], z[5], z[6], z[7]);
    }
}

extern "C" void kernel_launch(void* const* d_in, const int* in_sizes, int n_in,
                              void* d_out, int out_size) {
    const float* zm = (const float*)d_in[0];
    const float* lv = (const float*)d_in[1];
    const float* ep = (const float*)d_in[2];
    const float* W0 = (const float*)d_in[3];
    const float* b0 = (const float*)d_in[4];
    const float* W1 = (const float*)d_in[5];
    const float* b1 = (const float*)d_in[6];
    const float* W2 = (const float*)d_in[7];
    const float* b2 = (const float*)d_in[8];
    const float* Wo = (const float*)d_in[9];
    const float* bo = (const float*)d_in[10];

    int B = in_sizes[0] / 64;

    int smem = (8 * 4096 + 8 * 64) * (int)sizeof(float);  // 133120 B
    cudaFuncSetAttribute(iaf_kernel, cudaFuncAttributeMaxDynamicSharedMemorySize, smem);

    int grid = (B + RB - 1) / RB;
    iaf_kernel<<<grid, NT, smem>>>(zm, lv, ep, W0, b0, W1, b1, W2, b2, Wo, bo,
                                   (float*)d_out, B);
}

// round 4
// speedup vs baseline: 1.0477x; 1.0477x over previous
#include <cuda_runtime.h>
#include <math.h>
#include <stdint.h>

// IAF, 2 MADE flows, B=4096, D=H=64.
// Identity (verified R1, rel 5e-8): the reference forward scan is the exact
// inverse of z -> z - shift(z), so density = -0.5*D*log(2pi) - 0.5*sum(lv)
// - 0.5*sum(eps^2); only the inverse pass (8 masked [Bx64]@[64x64] GEMMs) runs.
// R4: warp-level mma.sync m16n8k8 tf32 (tcgen05 unusable: harness PTX target
// is compute_100, which rejects tcgen05). 2 compute warps x 16 rows per block.

#define NT   128
#define RB   32
#define AST  68   // activation row stride (floats), conflict-free A-frag LDS

// smem byte offsets
#define SM_BIAS  0
#define SM_W     2048                        // 8 matrices * 16384 B (frag-tiled)
#define SM_ACT   (2048 + 8 * 16384)          // 133120: 2 warps * 16*AST floats
#define SM_ZX    (SM_ACT + 2 * 16 * AST * 4) // exact-fp32 z buffer
#define SM_TOTAL (SM_ZX  + 2 * 16 * AST * 4) // 150528 B

static __device__ __forceinline__ float tf32r(float x) {
    uint32_t y;
    asm("cvt.rna.tf32.f32 %0, %1;" : "=r"(y) : "f"(x));
    return __uint_as_float(y);
}

static __device__ __forceinline__ void mma8(float* d, uint32_t a0, uint32_t a1,
                                            uint32_t a2, uint32_t a3,
                                            uint32_t b0, uint32_t b1) {
    asm volatile(
        "mma.sync.aligned.m16n8k8.row.col.f32.tf32.tf32.f32 "
        "{%0,%1,%2,%3}, {%4,%5,%6,%7}, {%8,%9}, {%0,%1,%2,%3};"
        : "+f"(d[0]), "+f"(d[1]), "+f"(d[2]), "+f"(d[3])
        : "r"(a0), "r"(a1), "r"(a2), "r"(a3), "r"(b0), "r"(b1));
}

__global__ __launch_bounds__(NT, 1)
void iaf_mma(const float* __restrict__ zm, const float* __restrict__ lv,
             const float* __restrict__ ep,
             const float* __restrict__ W0, const float* __restrict__ b0,
             const float* __restrict__ W1, const float* __restrict__ b1,
             const float* __restrict__ W2, const float* __restrict__ b2,
             const float* __restrict__ Wo, const float* __restrict__ bo,
             float* __restrict__ out, int B)
{
    extern __shared__ char smem[];
    const int tid = threadIdx.x;
    const int wid = tid >> 5;

    // ---- Preamble: masked, tf32-rounded, fragment-tiled weights into smem.
    // Tile layout per matrix (4096 floats): for k-block kb=k>>3, n-block nb=n>>3,
    // offset = (kb*8+nb)*64 + ((k&3)*8 + (n&7))*2 + ((k>>2)&1)
    // so a B-fragment (b0,b1) = (W[kb8+tig][nb8+g], W[kb8+tig+4][nb8+g]) is one
    // lane-linear float2 load.
    // d_h[h] = h % 63 + 1. Masks: m_in: k <= n%63 ; m_hid: k%63 <= n%63 ;
    // m_out: k%63 < n.
    for (int i = tid; i < 8192; i += NT) {          // float4 granules
        int e   = i << 2;
        int mat = e >> 12;                          // f*4 + l
        int f   = mat >> 2;
        int l   = mat & 3;
        int r   = e & 4095;
        int k   = r >> 6;
        int n0  = r & 63;
        const float* src = (l == 0) ? W0 : (l == 1) ? W1 : (l == 2) ? W2 : Wo;
        float4 w = *(const float4*)(src + f * 4096 + k * 64 + n0);
        float vals[4] = {w.x, w.y, w.z, w.w};
        int kb = k >> 3, k2 = k & 3, half = (k >> 2) & 1;
        int kmod = k % 63;
        float* dst = (float*)(smem + SM_W) + mat * 4096;
        #pragma unroll
        for (int q = 0; q < 4; ++q) {
            int n = n0 + q;
            bool keep = (l == 0) ? (k <= n % 63)
                      : (l == 3) ? (kmod < n)
                                 : (kmod <= n % 63);
            float v = keep ? tf32r(vals[q]) : 0.0f;
            dst[(kb * 8 + (n >> 3)) * 64 + (k2 * 8 + (n & 7)) * 2 + half] = v;
        }
    }
    for (int i = tid; i < 128; i += NT) {
        int f = i >> 6, j = i & 63;
        float* bs = (float*)(smem + SM_BIAS);
        bs[(f * 4 + 0) * 64 + j] = b0[i];
        bs[(f * 4 + 1) * 64 + j] = b1[i];
        bs[(f * 4 + 2) * 64 + j] = b2[i];
        bs[(f * 4 + 3) * 64 + j] = bo[i];
    }
    __syncthreads();
    if (wid >= 2) return;                 // warps 2,3 only helped the preamble

    // ---- Compute warps: warp w owns rows [rowbase, rowbase+16).
    const int lane = tid & 31;
    const int g    = lane >> 2;           // fragment group (row g, g+8)
    const int tig  = lane & 3;
    float* actW = (float*)(smem + SM_ACT) + wid * 16 * AST;  // tf32-rounded A
    float* zxW  = (float*)(smem + SM_ZX)  + wid * 16 * AST;  // exact fp32 z
    const int rowbase = blockIdx.x * RB + wid * 16;

    // ---- Init: z0 = zm + exp(0.5*lv)*eps ; density.
    {
        int r  = lane >> 1;
        int c0 = (lane & 1) * 32;
        bool v = (rowbase + r) < B;
        const size_t go = (size_t)(rowbase + r) * 64 + c0;
        float slv = 0.f, se2 = 0.f;
        #pragma unroll
        for (int q = 0; q < 8; ++q) {
            float4 a = v ? *(const float4*)(zm + go + q * 4) : make_float4(0,0,0,0);
            float4 b = v ? *(const float4*)(lv + go + q * 4) : make_float4(0,0,0,0);
            float4 c = v ? *(const float4*)(ep + go + q * 4) : make_float4(0,0,0,0);
            float z0 = a.x + expf(0.5f * b.x) * c.x;
            float z1 = a.y + expf(0.5f * b.y) * c.y;
            float z2 = a.z + expf(0.5f * b.z) * c.z;
            float z3 = a.w + expf(0.5f * b.w) * c.w;
            *(float4*)(zxW  + r * AST + c0 + q * 4) = make_float4(z0, z1, z2, z3);
            *(float4*)(actW + r * AST + c0 + q * 4) =
                make_float4(tf32r(z0), tf32r(z1), tf32r(z2), tf32r(z3));
            slv += b.x + b.y + b.z + b.w;
            se2 += c.x*c.x + c.y*c.y + c.z*c.z + c.w*c.w;
        }
        slv += __shfl_xor_sync(0xffffffffu, slv, 1);
        se2 += __shfl_xor_sync(0xffffffffu, se2, 1);
        if ((lane & 1) == 0 && v)
            out[(size_t)B * 64 + rowbase + r] =
                -58.81206612509905f - 0.5f * slv - 0.5f * se2;
    }
    __syncwarp();

    // z carried in D-fragment layout: zk[nb*4+{0..3}] = rows {g,g+8} cols
    // {nb*8+2tig, +1}
    float zk[32];
    #pragma unroll
    for (int nb = 0; nb < 8; ++nb) {
        float2 p0 = *(const float2*)(zxW + g * AST + nb * 8 + 2 * tig);
        float2 p1 = *(const float2*)(zxW + (g + 8) * AST + nb * 8 + 2 * tig);
        zk[nb*4+0] = p0.x; zk[nb*4+1] = p0.y;
        zk[nb*4+2] = p1.x; zk[nb*4+3] = p1.y;
    }

    // ---- 8 chained layers: flow 1 then flow 0 (reverse between flows).
    #pragma unroll 1
    for (int fi = 0; fi < 2; ++fi) {
        const int f = 1 - fi;
        #pragma unroll 1
        for (int l = 0; l < 4; ++l) {
            const float* wm = (const float*)(smem + SM_W) + (f * 4 + l) * 4096;
            float acc[32];
            #pragma unroll
            for (int i = 0; i < 32; ++i) acc[i] = 0.f;
            #pragma unroll
            for (int kb = 0; kb < 8; ++kb) {
                uint32_t a0 = __float_as_uint(actW[g * AST + kb * 8 + tig]);
                uint32_t a1 = __float_as_uint(actW[(g + 8) * AST + kb * 8 + tig]);
                uint32_t a2 = __float_as_uint(actW[g * AST + kb * 8 + tig + 4]);
                uint32_t a3 = __float_as_uint(actW[(g + 8) * AST + kb * 8 + tig + 4]);
                #pragma unroll
                for (int nb = 0; nb < 8; ++nb) {
                    float2 bfr = *(const float2*)(wm + (kb * 8 + nb) * 64 +
                                                  (tig * 8 + g) * 2);
                    mma8(acc + nb * 4, a0, a1, a2, a3,
                         __float_as_uint(bfr.x), __float_as_uint(bfr.y));
                }
            }
            const float* bias = (const float*)(smem + SM_BIAS) + (f * 4 + l) * 64;
            if (l < 3) {
                __syncwarp();            // all lanes done reading actW
                #pragma unroll
                for (int nb = 0; nb < 8; ++nb) {
                    float2 bb = *(const float2*)(bias + nb * 8 + 2 * tig);
                    float v0 = tf32r(fmaxf(acc[nb*4+0] + bb.x, 0.f));
                    float v1 = tf32r(fmaxf(acc[nb*4+1] + bb.y, 0.f));
                    float v2 = tf32r(fmaxf(acc[nb*4+2] + bb.x, 0.f));
                    float v3 = tf32r(fmaxf(acc[nb*4+3] + bb.y, 0.f));
                    *(float2*)(actW + g * AST + nb * 8 + 2 * tig) = make_float2(v0, v1);
                    *(float2*)(actW + (g + 8) * AST + nb * 8 + 2 * tig) = make_float2(v2, v3);
                }
                __syncwarp();
            } else {
                #pragma unroll
                for (int nb = 0; nb < 8; ++nb) {
                    float2 bb = *(const float2*)(bias + nb * 8 + 2 * tig);
                    zk[nb*4+0] -= acc[nb*4+0] + bb.x;
                    zk[nb*4+1] -= acc[nb*4+1] + bb.y;
                    zk[nb*4+2] -= acc[nb*4+2] + bb.x;
                    zk[nb*4+3] -= acc[nb*4+3] + bb.y;
                }
                if (fi == 0) {
                    // reverse cols: col c -> 63-c; pair (c1,c0) lands at 62-8nb-2tig
                    __syncwarp();
                    #pragma unroll
                    for (int nb = 0; nb < 8; ++nb) {
                        int cb = 62 - nb * 8 - 2 * tig;
                        *(float2*)(zxW + g * AST + cb) =
                            make_float2(zk[nb*4+1], zk[nb*4+0]);
                        *(float2*)(zxW + (g + 8) * AST + cb) =
                            make_float2(zk[nb*4+3], zk[nb*4+2]);
                        *(float2*)(actW + g * AST + cb) =
                            make_float2(tf32r(zk[nb*4+1]), tf32r(zk[nb*4+0]));
                        *(float2*)(actW + (g + 8) * AST + cb) =
                            make_float2(tf32r(zk[nb*4+3]), tf32r(zk[nb*4+2]));
                    }
                    __syncwarp();
                    #pragma unroll
                    for (int nb = 0; nb < 8; ++nb) {
                        float2 p0 = *(const float2*)(zxW + g * AST + nb * 8 + 2 * tig);
                        float2 p1 = *(const float2*)(zxW + (g + 8) * AST + nb * 8 + 2 * tig);
                        zk[nb*4+0] = p0.x; zk[nb*4+1] = p0.y;
                        zk[nb*4+2] = p1.x; zk[nb*4+3] = p1.y;
                    }
                }
            }
        }
    }

    // ---- Write samples (D-fragment layout -> gmem float2 stores).
    #pragma unroll
    for (int nb = 0; nb < 8; ++nb) {
        int r0 = rowbase + g, r1 = rowbase + g + 8;
        if (r0 < B)
            *(float2*)(out + (size_t)r0 * 64 + nb * 8 + 2 * tig) =
                make_float2(zk[nb*4+0], zk[nb*4+1]);
        if (r1 < B)
            *(float2*)(out + (size_t)r1 * 64 + nb * 8 + 2 * tig) =
                make_float2(zk[nb*4+2], zk[nb*4+3]);
    }
}

extern "C" void kernel_launch(void* const* d_in, const int* in_sizes, int n_in,
                              void* d_out, int out_size) {
    const float* zm = (const float*)d_in[0];
    const float* lv = (const float*)d_in[1];
    const float* ep = (const float*)d_in[2];
    const float* W0 = (const float*)d_in[3];
    const float* b0 = (const float*)d_in[4];
    const float* W1 = (const float*)d_in[5];
    const float* b1 = (const float*)d_in[6];
    const float* W2 = (const float*)d_in[7];
    const float* b2 = (const float*)d_in[8];
    const float* Wo = (const float*)d_in[9];
    const float* bo = (const float*)d_in[10];

    int B = in_sizes[0] / 64;

    cudaFuncSetAttribute(iaf_mma, cudaFuncAttributeMaxDynamicSharedMemorySize,
                         SM_TOTAL);
    int grid = (B + RB - 1) / RB;
    iaf_mma<<<grid, NT, SM_TOTAL>>>(zm, lv, ep, W0, b0, W1, b1, W2, b2, Wo, bo,
                                    (float*)d_out, B);
}

// round 5
// speedup vs baseline: 2.1335x; 2.0364x over previous
#include <cuda_runtime.h>
#include <math.h>
#include <stdint.h>

// IAF, 2 MADE flows, B=4096, D=H=64.
// Identity (verified R1/R4): reference forward scan is the exact inverse of
// z -> z - shift(z), so density = -0.5*D*log(2pi) - 0.5*sum(lv) - 0.5*sum(eps^2)
// and only the inverse pass (8 masked [Bx64]@[64x64] GEMMs) needs compute.
// R5: prep kernel pre-tiles masked tf32 weights into global scratch (B-fragment
// layout, coalesced LDG.64). Main kernel: 1 warp / 32 rows / block, weights
// streamed from L2 into registers, activations transposed via shuffles,
// zero smem staging, zero barriers.

#define C_DENS (-58.81206612509905f)

__device__ float2 g_wfrag[8 * 64 * 32];   // 128 KB: [mat][kb*8+nb][lane]

static __device__ __forceinline__ float tf32r(float x) {
    uint32_t y;
    asm("cvt.rna.tf32.f32 %0, %1;" : "=r"(y) : "f"(x));
    return __uint_as_float(y);
}

static __device__ __forceinline__ void mma8(float* d, const float* a, float2 b) {
    asm volatile(
        "mma.sync.aligned.m16n8k8.row.col.f32.tf32.tf32.f32 "
        "{%0,%1,%2,%3}, {%4,%5,%6,%7}, {%8,%9}, {%0,%1,%2,%3};"
        : "+f"(d[0]), "+f"(d[1]), "+f"(d[2]), "+f"(d[3])
        : "r"(__float_as_uint(a[0])), "r"(__float_as_uint(a[1])),
          "r"(__float_as_uint(a[2])), "r"(__float_as_uint(a[3])),
          "r"(__float_as_uint(b.x)), "r"(__float_as_uint(b.y)));
}

// Build next-layer A-frags (tf32) from D-frag-layout values dv[nb*4+q].
static __device__ __forceinline__ void buildA(const float* dv, float* A, int lane) {
    const int tig  = lane & 3;
    const int srcA = (lane & ~3) | (tig >> 1);
    const int srcB = srcA + 2;
    const bool hi  = tig & 1;
    #pragma unroll
    for (int kb = 0; kb < 8; ++kb) {
        float d0 = dv[kb*4+0], d1 = dv[kb*4+1], d2 = dv[kb*4+2], d3 = dv[kb*4+3];
        float t00 = __shfl_sync(0xffffffffu, d0, srcA);
        float t01 = __shfl_sync(0xffffffffu, d1, srcA);
        float t10 = __shfl_sync(0xffffffffu, d2, srcA);
        float t11 = __shfl_sync(0xffffffffu, d3, srcA);
        float t20 = __shfl_sync(0xffffffffu, d0, srcB);
        float t21 = __shfl_sync(0xffffffffu, d1, srcB);
        float t30 = __shfl_sync(0xffffffffu, d2, srcB);
        float t31 = __shfl_sync(0xffffffffu, d3, srcB);
        A[kb*4+0] = tf32r(hi ? t01 : t00);
        A[kb*4+1] = tf32r(hi ? t11 : t10);
        A[kb*4+2] = tf32r(hi ? t21 : t20);
        A[kb*4+3] = tf32r(hi ? t31 : t30);
    }
}

// In-place reversal of z (D-frag layout) along the 64-column axis.
static __device__ __forceinline__ void reverse_z(float* zk, int lane) {
    const int srcR = (lane & ~3) | (3 - (lane & 3));
    float t[32];
    #pragma unroll
    for (int nb = 0; nb < 8; ++nb) {
        t[nb*4+0] = __shfl_sync(0xffffffffu, zk[(7-nb)*4+1], srcR);
        t[nb*4+1] = __shfl_sync(0xffffffffu, zk[(7-nb)*4+0], srcR);
        t[nb*4+2] = __shfl_sync(0xffffffffu, zk[(7-nb)*4+3], srcR);
        t[nb*4+3] = __shfl_sync(0xffffffffu, zk[(7-nb)*4+2], srcR);
    }
    #pragma unroll
    for (int i = 0; i < 32; ++i) zk[i] = t[i];
}

// ---- Prep: mask + tf32-round + tile weights into B-fragment layout.
// b0 = masked W[f][kb*8+tig][nb*8+g], b1 = same with +4 on k.
__global__ void prep_kernel(const float* __restrict__ W0,
                            const float* __restrict__ W1,
                            const float* __restrict__ W2,
                            const float* __restrict__ Wo) {
    int idx  = blockIdx.x * 256 + threadIdx.x;    // 0..16383
    int lane = idx & 31;
    int frag = (idx >> 5) & 63;
    int mat  = idx >> 11;                          // f*4 + l
    int f = mat >> 2, l = mat & 3;
    int kb = frag >> 3, nb = frag & 7;
    int g = lane >> 2, tig = lane & 3;
    int n = nb * 8 + g;
    const float* src = (l == 0) ? W0 : (l == 1) ? W1 : (l == 2) ? W2 : Wo;
    src += f * 4096;
    int k0 = kb * 8 + tig, k1 = k0 + 4;
    bool m0, m1;
    if (l == 0)      { m0 = (k0 <= n % 63);        m1 = (k1 <= n % 63); }
    else if (l == 3) { m0 = ((k0 % 63) < n);       m1 = ((k1 % 63) < n); }
    else             { m0 = ((k0 % 63) <= n % 63); m1 = ((k1 % 63) <= n % 63); }
    float b0v = m0 ? tf32r(src[k0 * 64 + n]) : 0.0f;
    float b1v = m1 ? tf32r(src[k1 * 64 + n]) : 0.0f;
    g_wfrag[idx] = make_float2(b0v, b1v);
}

__global__ __launch_bounds__(32, 1)
void iaf_main(const float* __restrict__ zm, const float* __restrict__ lv,
              const float* __restrict__ ep,
              const float* __restrict__ bp0, const float* __restrict__ bp1,
              const float* __restrict__ bp2, const float* __restrict__ bpo,
              float* __restrict__ out, int B)
{
    __shared__ float4 zsm[16 * 32];     // exact-fp32 z, [tile*8+nb][lane]
    const int lane = threadIdx.x;
    const int g = lane >> 2, tig = lane & 3;
    const int base = blockIdx.x * 32;

    float A0[32], A1[32];

    // ---- Init both tiles: z0 = zm + exp(0.5*lv)*eps ; density.
    #pragma unroll
    for (int t = 0; t < 2; ++t) {
        const int r0 = base + t * 16 + g;
        const int r1 = r0 + 8;
        const bool v0 = r0 < B, v1 = r1 < B;
        float zk[32];
        float sl0 = 0.f, se0 = 0.f, sl1 = 0.f, se1 = 0.f;
        #pragma unroll
        for (int nb = 0; nb < 8; ++nb) {
            const int col = nb * 8 + 2 * tig;
            float2 a0 = v0 ? *(const float2*)(zm + (size_t)r0*64 + col) : make_float2(0,0);
            float2 l0 = v0 ? *(const float2*)(lv + (size_t)r0*64 + col) : make_float2(0,0);
            float2 e0 = v0 ? *(const float2*)(ep + (size_t)r0*64 + col) : make_float2(0,0);
            float2 a1 = v1 ? *(const float2*)(zm + (size_t)r1*64 + col) : make_float2(0,0);
            float2 l1 = v1 ? *(const float2*)(lv + (size_t)r1*64 + col) : make_float2(0,0);
            float2 e1 = v1 ? *(const float2*)(ep + (size_t)r1*64 + col) : make_float2(0,0);
            zk[nb*4+0] = a0.x + __expf(0.5f * l0.x) * e0.x;
            zk[nb*4+1] = a0.y + __expf(0.5f * l0.y) * e0.y;
            zk[nb*4+2] = a1.x + __expf(0.5f * l1.x) * e1.x;
            zk[nb*4+3] = a1.y + __expf(0.5f * l1.y) * e1.y;
            sl0 += l0.x + l0.y;  se0 += e0.x*e0.x + e0.y*e0.y;
            sl1 += l1.x + l1.y;  se1 += e1.x*e1.x + e1.y*e1.y;
        }
        #pragma unroll
        for (int m = 1; m <= 2; m <<= 1) {
            sl0 += __shfl_xor_sync(0xffffffffu, sl0, m);
            se0 += __shfl_xor_sync(0xffffffffu, se0, m);
            sl1 += __shfl_xor_sync(0xffffffffu, sl1, m);
            se1 += __shfl_xor_sync(0xffffffffu, se1, m);
        }
        if (tig == 0) {
            if (v0) out[(size_t)B*64 + r0] = C_DENS - 0.5f*sl0 - 0.5f*se0;
            if (v1) out[(size_t)B*64 + r1] = C_DENS - 0.5f*sl1 - 0.5f*se1;
        }
        #pragma unroll
        for (int nb = 0; nb < 8; ++nb)
            zsm[(t*8+nb)*32 + lane] =
                make_float4(zk[nb*4+0], zk[nb*4+1], zk[nb*4+2], zk[nb*4+3]);
        buildA(zk, t ? A1 : A0, lane);
    }

    // ---- 8 chained layers: flow 1 then flow 0 (reverse between flows).
    #pragma unroll 1
    for (int fi = 0; fi < 2; ++fi) {
        const int f = 1 - fi;
        #pragma unroll 1
        for (int l = 0; l < 4; ++l) {
            const float2* wf = g_wfrag + ((f*4 + l) * 64) * 32;
            const float* bl = (l == 0) ? bp0 : (l == 1) ? bp1 : (l == 2) ? bp2 : bpo;
            float2 bias[8];
            #pragma unroll
            for (int nb = 0; nb < 8; ++nb)
                bias[nb] = *(const float2*)(bl + f*64 + nb*8 + 2*tig);

            float acc0[32], acc1[32];
            #pragma unroll
            for (int i = 0; i < 32; ++i) { acc0[i] = 0.f; acc1[i] = 0.f; }

            float2 Bb[2][8];
            #pragma unroll
            for (int nb = 0; nb < 8; ++nb) Bb[0][nb] = wf[nb*32 + lane];
            #pragma unroll
            for (int kb = 0; kb < 8; ++kb) {
                if (kb < 7) {
                    #pragma unroll
                    for (int nb = 0; nb < 8; ++nb)
                        Bb[(kb+1)&1][nb] = wf[((kb+1)*8 + nb)*32 + lane];
                }
                #pragma unroll
                for (int nb = 0; nb < 8; ++nb) {
                    float2 bfr = Bb[kb&1][nb];
                    mma8(acc0 + nb*4, A0 + kb*4, bfr);
                    mma8(acc1 + nb*4, A1 + kb*4, bfr);
                }
            }

            if (l < 3) {
                #pragma unroll
                for (int nb = 0; nb < 8; ++nb) {
                    acc0[nb*4+0] = fmaxf(acc0[nb*4+0] + bias[nb].x, 0.f);
                    acc0[nb*4+1] = fmaxf(acc0[nb*4+1] + bias[nb].y, 0.f);
                    acc0[nb*4+2] = fmaxf(acc0[nb*4+2] + bias[nb].x, 0.f);
                    acc0[nb*4+3] = fmaxf(acc0[nb*4+3] + bias[nb].y, 0.f);
                    acc1[nb*4+0] = fmaxf(acc1[nb*4+0] + bias[nb].x, 0.f);
                    acc1[nb*4+1] = fmaxf(acc1[nb*4+1] + bias[nb].y, 0.f);
                    acc1[nb*4+2] = fmaxf(acc1[nb*4+2] + bias[nb].x, 0.f);
                    acc1[nb*4+3] = fmaxf(acc1[nb*4+3] + bias[nb].y, 0.f);
                }
                buildA(acc0, A0, lane);
                buildA(acc1, A1, lane);
            } else {
                #pragma unroll
                for (int t = 0; t < 2; ++t) {
                    float* acc = t ? acc1 : acc0;
                    float zk[32];
                    #pragma unroll
                    for (int nb = 0; nb < 8; ++nb) {
                        float4 z4 = zsm[(t*8+nb)*32 + lane];
                        zk[nb*4+0] = z4.x - (acc[nb*4+0] + bias[nb].x);
                        zk[nb*4+1] = z4.y - (acc[nb*4+1] + bias[nb].y);
                        zk[nb*4+2] = z4.z - (acc[nb*4+2] + bias[nb].x);
                        zk[nb*4+3] = z4.w - (acc[nb*4+3] + bias[nb].y);
                    }
                    if (fi == 0) {
                        reverse_z(zk, lane);
                        #pragma unroll
                        for (int nb = 0; nb < 8; ++nb)
                            zsm[(t*8+nb)*32 + lane] =
                                make_float4(zk[nb*4+0], zk[nb*4+1],
                                            zk[nb*4+2], zk[nb*4+3]);
                        buildA(zk, t ? A1 : A0, lane);
                    } else {
                        const int r0 = base + t * 16 + g;
                        const int r1 = r0 + 8;
                        #pragma unroll
                        for (int nb = 0; nb < 8; ++nb) {
                            const int col = nb * 8 + 2 * tig;
                            if (r0 < B)
                                *(float2*)(out + (size_t)r0*64 + col) =
                                    make_float2(zk[nb*4+0], zk[nb*4+1]);
                            if (r1 < B)
                                *(float2*)(out + (size_t)r1*64 + col) =
                                    make_float2(zk[nb*4+2], zk[nb*4+3]);
                        }
                    }
                }
            }
        }
    }
}

extern "C" void kernel_launch(void* const* d_in, const int* in_sizes, int n_in,
                              void* d_out, int out_size) {
    const float* zm = (const float*)d_in[0];
    const float* lv = (const float*)d_in[1];
    const float* ep = (const float*)d_in[2];
    const float* W0 = (const float*)d_in[3];
    const float* b0 = (const float*)d_in[4];
    const float* W1 = (const float*)d_in[5];
    const float* b1 = (const float*)d_in[6];
    const float* W2 = (const float*)d_in[7];
    const float* b2 = (const float*)d_in[8];
    const float* Wo = (const float*)d_in[9];
    const float* bo = (const float*)d_in[10];

    int B = in_sizes[0] / 64;

    prep_kernel<<<64, 256>>>(W0, W1, W2, Wo);
    int grid = (B + 31) / 32;
    iaf_main<<<grid, 32>>>(zm, lv, ep, b0, b1, b2, bo, (float*)d_out, B);
}

// round 6
// speedup vs baseline: 2.7301x; 1.2796x over previous
#include <cuda_runtime.h>
#include <math.h>
#include <stdint.h>

// IAF, 2 MADE flows, B=4096, D=H=64.
// Identity (verified R1/R4/R5): the reference forward scan is the exact inverse
// of z -> z - shift(z), so density = -0.5*D*log(2pi) - 0.5*sum(lv)
// - 0.5*sum(eps^2); only the inverse pass (8 masked [Bx64]@[64x64] GEMMs) runs.
// R6: prep kernel pre-tiles masked tf32 weights into global scratch (coalesced
// B-fragment layout). Main kernel: 2 warps/block, ONE m16 tile per warp
// (regs ~130, no spills), weights streamed from L2, activation transposes via
// shuffles (raw f32 bits -> MMA truncates to tf32), zero block barriers.

#define C_DENS (-58.81206612509905f)

__device__ float2 g_wfrag[8 * 64 * 32];   // 128 KB: [mat][kb*8+nb][lane]

static __device__ __forceinline__ float tf32r(float x) {
    uint32_t y;
    asm("cvt.rna.tf32.f32 %0, %1;" : "=r"(y) : "f"(x));
    return __uint_as_float(y);
}

static __device__ __forceinline__ void mma8(float* d, const float* a, float2 b) {
    asm volatile(
        "mma.sync.aligned.m16n8k8.row.col.f32.tf32.tf32.f32 "
        "{%0,%1,%2,%3}, {%4,%5,%6,%7}, {%8,%9}, {%0,%1,%2,%3};"
        : "+f"(d[0]), "+f"(d[1]), "+f"(d[2]), "+f"(d[3])
        : "r"(__float_as_uint(a[0])), "r"(__float_as_uint(a[1])),
          "r"(__float_as_uint(a[2])), "r"(__float_as_uint(a[3])),
          "r"(__float_as_uint(b.x)), "r"(__float_as_uint(b.y)));
}

// Next-layer A-frags from D-frag-layout values dv[nb*4+q].
// Raw f32 bits are fed to the MMA (HW truncates to tf32; accuracy margin
// is ~1e3x per R5's rel_err of 7.5e-7).
static __device__ __forceinline__ void buildA(const float* dv, float* A, int lane) {
    const int tig  = lane & 3;
    const int srcA = (lane & ~3) | (tig >> 1);
    const int srcB = srcA + 2;
    const bool hi  = tig & 1;
    #pragma unroll
    for (int kb = 0; kb < 8; ++kb) {
        float d0 = dv[kb*4+0], d1 = dv[kb*4+1], d2 = dv[kb*4+2], d3 = dv[kb*4+3];
        float t00 = __shfl_sync(0xffffffffu, d0, srcA);
        float t01 = __shfl_sync(0xffffffffu, d1, srcA);
        float t10 = __shfl_sync(0xffffffffu, d2, srcA);
        float t11 = __shfl_sync(0xffffffffu, d3, srcA);
        float t20 = __shfl_sync(0xffffffffu, d0, srcB);
        float t21 = __shfl_sync(0xffffffffu, d1, srcB);
        float t30 = __shfl_sync(0xffffffffu, d2, srcB);
        float t31 = __shfl_sync(0xffffffffu, d3, srcB);
        A[kb*4+0] = hi ? t01 : t00;
        A[kb*4+1] = hi ? t11 : t10;
        A[kb*4+2] = hi ? t21 : t20;
        A[kb*4+3] = hi ? t31 : t30;
    }
}

// In-place reversal of z (D-frag layout) along the 64-column axis.
static __device__ __forceinline__ void reverse_z(float* zk, int lane) {
    const int srcR = (lane & ~3) | (3 - (lane & 3));
    float t[32];
    #pragma unroll
    for (int nb = 0; nb < 8; ++nb) {
        t[nb*4+0] = __shfl_sync(0xffffffffu, zk[(7-nb)*4+1], srcR);
        t[nb*4+1] = __shfl_sync(0xffffffffu, zk[(7-nb)*4+0], srcR);
        t[nb*4+2] = __shfl_sync(0xffffffffu, zk[(7-nb)*4+3], srcR);
        t[nb*4+3] = __shfl_sync(0xffffffffu, zk[(7-nb)*4+2], srcR);
    }
    #pragma unroll
    for (int i = 0; i < 32; ++i) zk[i] = t[i];
}

// ---- Prep: mask + tf32-round + tile weights into B-fragment layout.
__global__ void prep_kernel(const float* __restrict__ W0,
                            const float* __restrict__ W1,
                            const float* __restrict__ W2,
                            const float* __restrict__ Wo) {
    int idx  = blockIdx.x * 256 + threadIdx.x;    // 0..16383
    int lane = idx & 31;
    int frag = (idx >> 5) & 63;
    int mat  = idx >> 11;                          // f*4 + l
    int f = mat >> 2, l = mat & 3;
    int kb = frag >> 3, nb = frag & 7;
    int g = lane >> 2, tig = lane & 3;
    int n = nb * 8 + g;
    const float* src = (l == 0) ? W0 : (l == 1) ? W1 : (l == 2) ? W2 : Wo;
    src += f * 4096;
    int k0 = kb * 8 + tig, k1 = k0 + 4;
    bool m0, m1;
    if (l == 0)      { m0 = (k0 <= n % 63);        m1 = (k1 <= n % 63); }
    else if (l == 3) { m0 = ((k0 % 63) < n);       m1 = ((k1 % 63) < n); }
    else             { m0 = ((k0 % 63) <= n % 63); m1 = ((k1 % 63) <= n % 63); }
    float b0v = m0 ? tf32r(src[k0 * 64 + n]) : 0.0f;
    float b1v = m1 ? tf32r(src[k1 * 64 + n]) : 0.0f;
    g_wfrag[idx] = make_float2(b0v, b1v);
}

__global__ __launch_bounds__(64, 1)
void iaf_main(const float* __restrict__ zm, const float* __restrict__ lv,
              const float* __restrict__ ep,
              const float* __restrict__ bp0, const float* __restrict__ bp1,
              const float* __restrict__ bp2, const float* __restrict__ bpo,
              float* __restrict__ out, int B)
{
    __shared__ float4 zsm[2][8][32];     // exact-fp32 z, per warp
    const int lane = threadIdx.x & 31;
    const int wid  = threadIdx.x >> 5;
    const int g = lane >> 2, tig = lane & 3;
    const int base = blockIdx.x * 32 + wid * 16;

    float A[32];

    // ---- Init: z0 = zm + exp(0.5*lv)*eps ; density.
    {
        const int r0 = base + g;
        const int r1 = r0 + 8;
        const bool v0 = r0 < B, v1 = r1 < B;
        float zk[32];
        float sl0 = 0.f, se0 = 0.f, sl1 = 0.f, se1 = 0.f;
        #pragma unroll
        for (int nb = 0; nb < 8; ++nb) {
            const int col = nb * 8 + 2 * tig;
            float2 a0 = v0 ? *(const float2*)(zm + (size_t)r0*64 + col) : make_float2(0,0);
            float2 l0 = v0 ? *(const float2*)(lv + (size_t)r0*64 + col) : make_float2(0,0);
            float2 e0 = v0 ? *(const float2*)(ep + (size_t)r0*64 + col) : make_float2(0,0);
            float2 a1 = v1 ? *(const float2*)(zm + (size_t)r1*64 + col) : make_float2(0,0);
            float2 l1 = v1 ? *(const float2*)(lv + (size_t)r1*64 + col) : make_float2(0,0);
            float2 e1 = v1 ? *(const float2*)(ep + (size_t)r1*64 + col) : make_float2(0,0);
            zk[nb*4+0] = a0.x + __expf(0.5f * l0.x) * e0.x;
            zk[nb*4+1] = a0.y + __expf(0.5f * l0.y) * e0.y;
            zk[nb*4+2] = a1.x + __expf(0.5f * l1.x) * e1.x;
            zk[nb*4+3] = a1.y + __expf(0.5f * l1.y) * e1.y;
            sl0 += l0.x + l0.y;  se0 += e0.x*e0.x + e0.y*e0.y;
            sl1 += l1.x + l1.y;  se1 += e1.x*e1.x + e1.y*e1.y;
        }
        #pragma unroll
        for (int m = 1; m <= 2; m <<= 1) {
            sl0 += __shfl_xor_sync(0xffffffffu, sl0, m);
            se0 += __shfl_xor_sync(0xffffffffu, se0, m);
            sl1 += __shfl_xor_sync(0xffffffffu, sl1, m);
            se1 += __shfl_xor_sync(0xffffffffu, se1, m);
        }
        if (tig == 0) {
            if (v0) out[(size_t)B*64 + r0] = C_DENS - 0.5f*sl0 - 0.5f*se0;
            if (v1) out[(size_t)B*64 + r1] = C_DENS - 0.5f*sl1 - 0.5f*se1;
        }
        #pragma unroll
        for (int nb = 0; nb < 8; ++nb)
            zsm[wid][nb][lane] =
                make_float4(zk[nb*4+0], zk[nb*4+1], zk[nb*4+2], zk[nb*4+3]);
        buildA(zk, A, lane);
    }

    // ---- 8 chained layers: flow 1 then flow 0 (reverse between flows).
    #pragma unroll 1
    for (int fi = 0; fi < 2; ++fi) {
        const int f = 1 - fi;
        #pragma unroll 1
        for (int l = 0; l < 4; ++l) {
            const float2* wf = g_wfrag + ((f*4 + l) * 64) * 32;
            const float* bl = (l == 0) ? bp0 : (l == 1) ? bp1 : (l == 2) ? bp2 : bpo;
            float2 bias[8];
            #pragma unroll
            for (int nb = 0; nb < 8; ++nb)
                bias[nb] = *(const float2*)(bl + f*64 + nb*8 + 2*tig);

            float acc[32];
            #pragma unroll
            for (int i = 0; i < 32; ++i) acc[i] = 0.f;

            float2 Bb[2][8];
            #pragma unroll
            for (int nb = 0; nb < 8; ++nb) Bb[0][nb] = wf[nb*32 + lane];
            #pragma unroll
            for (int kb = 0; kb < 8; ++kb) {
                if (kb < 7) {
                    #pragma unroll
                    for (int nb = 0; nb < 8; ++nb)
                        Bb[(kb+1)&1][nb] = wf[((kb+1)*8 + nb)*32 + lane];
                }
                #pragma unroll
                for (int nb = 0; nb < 8; ++nb)
                    mma8(acc + nb*4, A + kb*4, Bb[kb&1][nb]);
            }

            if (l < 3) {
                #pragma unroll
                for (int nb = 0; nb < 8; ++nb) {
                    acc[nb*4+0] = fmaxf(acc[nb*4+0] + bias[nb].x, 0.f);
                    acc[nb*4+1] = fmaxf(acc[nb*4+1] + bias[nb].y, 0.f);
                    acc[nb*4+2] = fmaxf(acc[nb*4+2] + bias[nb].x, 0.f);
                    acc[nb*4+3] = fmaxf(acc[nb*4+3] + bias[nb].y, 0.f);
                }
                buildA(acc, A, lane);
            } else {
                float zk[32];
                #pragma unroll
                for (int nb = 0; nb < 8; ++nb) {
                    float4 z4 = zsm[wid][nb][lane];
                    zk[nb*4+0] = z4.x - (acc[nb*4+0] + bias[nb].x);
                    zk[nb*4+1] = z4.y - (acc[nb*4+1] + bias[nb].y);
                    zk[nb*4+2] = z4.z - (acc[nb*4+2] + bias[nb].x);
                    zk[nb*4+3] = z4.w - (acc[nb*4+3] + bias[nb].y);
                }
                if (fi == 0) {
                    reverse_z(zk, lane);
                    #pragma unroll
                    for (int nb = 0; nb < 8; ++nb)
                        zsm[wid][nb][lane] =
                            make_float4(zk[nb*4+0], zk[nb*4+1],
                                        zk[nb*4+2], zk[nb*4+3]);
                    buildA(zk, A, lane);
                } else {
                    const int r0 = base + g;
                    const int r1 = r0 + 8;
                    #pragma unroll
                    for (int nb = 0; nb < 8; ++nb) {
                        const int col = nb * 8 + 2 * tig;
                        if (r0 < B)
                            *(float2*)(out + (size_t)r0*64 + col) =
                                make_float2(zk[nb*4+0], zk[nb*4+1]);
                        if (r1 < B)
                            *(float2*)(out + (size_t)r1*64 + col) =
                                make_float2(zk[nb*4+2], zk[nb*4+3]);
                    }
                }
            }
        }
    }
}

extern "C" void kernel_launch(void* const* d_in, const int* in_sizes, int n_in,
                              void* d_out, int out_size) {
    const float* zm = (const float*)d_in[0];
    const float* lv = (const float*)d_in[1];
    const float* ep = (const float*)d_in[2];
    const float* W0 = (const float*)d_in[3];
    const float* b0 = (const float*)d_in[4];
    const float* W1 = (const float*)d_in[5];
    const float* b1 = (const float*)d_in[6];
    const float* W2 = (const float*)d_in[7];
    const float* b2 = (const float*)d_in[8];
    const float* Wo = (const float*)d_in[9];
    const float* bo = (const float*)d_in[10];

    int B = in_sizes[0] / 64;

    prep_kernel<<<64, 256>>>(W0, W1, W2, Wo);
    int grid = (B + 31) / 32;
    iaf_main<<<grid, 64>>>(zm, lv, ep, b0, b1, b2, bo, (float*)d_out, B);
}

// round 7
// speedup vs baseline: 3.1314x; 1.1470x over previous
#include <cuda_runtime.h>
#include <math.h>
#include <stdint.h>

// IAF, 2 MADE flows, B=4096, D=H=64.
// Identity (verified R1/R4/R5/R6): the reference forward scan is the exact
// inverse of z -> z - shift(z), so density = -0.5*D*log(2pi) - 0.5*sum(lv)
// - 0.5*sum(eps^2); only the inverse pass (8 masked [Bx64]@[64x64] GEMMs) runs.
// R7: split-N. Block = 128 thr = 4 warps; warp (p,h) computes tile p (16 rows),
// output cols [32h,32h+32). Activations exchanged via padded smem (stride 68:
// conflict-free A-frag LDS); weights from L2 in B-frag layout (prep kernel).

#define C_DENS (-58.81206612509905f)
#define AST 68

__device__ float2 g_wfrag[8 * 64 * 32];   // 128 KB: [mat][kb*8+nb][lane]

static __device__ __forceinline__ float tf32r(float x) {
    uint32_t y;
    asm("cvt.rna.tf32.f32 %0, %1;" : "=r"(y) : "f"(x));
    return __uint_as_float(y);
}

static __device__ __forceinline__ void mma8(float* d, const float* a, float2 b) {
    asm volatile(
        "mma.sync.aligned.m16n8k8.row.col.f32.tf32.tf32.f32 "
        "{%0,%1,%2,%3}, {%4,%5,%6,%7}, {%8,%9}, {%0,%1,%2,%3};"
        : "+f"(d[0]), "+f"(d[1]), "+f"(d[2]), "+f"(d[3])
        : "r"(__float_as_uint(a[0])), "r"(__float_as_uint(a[1])),
          "r"(__float_as_uint(a[2])), "r"(__float_as_uint(a[3])),
          "r"(__float_as_uint(b.x)), "r"(__float_as_uint(b.y)));
}

// ---- Prep: mask + tf32-round + tile weights into B-fragment layout.
// b0 = masked W[f][kb*8+tig][nb*8+g], b1 = same with +4 on k.
__global__ void prep_kernel(const float* __restrict__ W0,
                            const float* __restrict__ W1,
                            const float* __restrict__ W2,
                            const float* __restrict__ Wo) {
    int idx  = blockIdx.x * 256 + threadIdx.x;    // 0..16383
    int lane = idx & 31;
    int frag = (idx >> 5) & 63;
    int mat  = idx >> 11;                          // f*4 + l
    int f = mat >> 2, l = mat & 3;
    int kb = frag >> 3, nb = frag & 7;
    int g = lane >> 2, tig = lane & 3;
    int n = nb * 8 + g;
    const float* src = (l == 0) ? W0 : (l == 1) ? W1 : (l == 2) ? W2 : Wo;
    src += f * 4096;
    int k0 = kb * 8 + tig, k1 = k0 + 4;
    bool m0, m1;
    if (l == 0)      { m0 = (k0 <= n % 63);        m1 = (k1 <= n % 63); }
    else if (l == 3) { m0 = ((k0 % 63) < n);       m1 = ((k1 % 63) < n); }
    else             { m0 = ((k0 % 63) <= n % 63); m1 = ((k1 % 63) <= n % 63); }
    float b0v = m0 ? tf32r(src[k0 * 64 + n]) : 0.0f;
    float b1v = m1 ? tf32r(src[k1 * 64 + n]) : 0.0f;
    g_wfrag[idx] = make_float2(b0v, b1v);
}

__global__ __launch_bounds__(128, 1)
void iaf_main(const float* __restrict__ zm, const float* __restrict__ lv,
              const float* __restrict__ ep,
              const float* __restrict__ bp0, const float* __restrict__ bp1,
              const float* __restrict__ bp2, const float* __restrict__ bpo,
              float* __restrict__ out, int B)
{
    __shared__ float act[2][16][AST];    // current activations (A operand)
    __shared__ float zbuf[2][16][AST];   // exact-fp32 z
    const int t = threadIdx.x;

    // ---- Init (block-cooperative): z0 = zm + exp(0.5*lv)*eps ; density.
    {
        int r = t >> 2, seg = t & 3;
        int pi = r >> 4, ri = r & 15;
        int gr = blockIdx.x * 32 + r;
        bool v = gr < B;
        float slv = 0.f, se2 = 0.f;
        #pragma unroll
        for (int q = 0; q < 4; ++q) {
            int col = seg * 16 + q * 4;
            const size_t go = (size_t)gr * 64 + col;
            float4 a = v ? *(const float4*)(zm + go) : make_float4(0,0,0,0);
            float4 b = v ? *(const float4*)(lv + go) : make_float4(0,0,0,0);
            float4 c = v ? *(const float4*)(ep + go) : make_float4(0,0,0,0);
            float4 z4;
            z4.x = a.x + __expf(0.5f * b.x) * c.x;
            z4.y = a.y + __expf(0.5f * b.y) * c.y;
            z4.z = a.z + __expf(0.5f * b.z) * c.z;
            z4.w = a.w + __expf(0.5f * b.w) * c.w;
            *(float4*)&act[pi][ri][col]  = z4;
            *(float4*)&zbuf[pi][ri][col] = z4;
            slv += b.x + b.y + b.z + b.w;
            se2 += c.x*c.x + c.y*c.y + c.z*c.z + c.w*c.w;
        }
        slv += __shfl_xor_sync(0xffffffffu, slv, 1);
        se2 += __shfl_xor_sync(0xffffffffu, se2, 1);
        slv += __shfl_xor_sync(0xffffffffu, slv, 2);
        se2 += __shfl_xor_sync(0xffffffffu, se2, 2);
        if (seg == 0 && v)
            out[(size_t)B * 64 + gr] = C_DENS - 0.5f * slv - 0.5f * se2;
    }
    __syncthreads();

    const int lane = t & 31, wid = t >> 5;
    const int p = wid >> 1, h = wid & 1;        // tile, column half
    const int g = lane >> 2, tig = lane & 3;
    const int rowbase = blockIdx.x * 32 + p * 16;

    // ---- 8 chained layers: flow 1 then flow 0 (reverse between flows).
    #pragma unroll 1
    for (int fi = 0; fi < 2; ++fi) {
        const int f = 1 - fi;
        #pragma unroll 1
        for (int l = 0; l < 4; ++l) {
            // B-fragments for this warp's 4 n-blocks (global nb = 4h+nb').
            const float2* wf = g_wfrag + (f * 4 + l) * 2048 + 4 * h * 32 + lane;
            float2 Bf[32];
            #pragma unroll
            for (int kb = 0; kb < 8; ++kb)
                #pragma unroll
                for (int nb = 0; nb < 4; ++nb)
                    Bf[kb*4+nb] = wf[kb * 256 + nb * 32];

            // A-fragments from act[p] (conflict-free: bank = 4g+tig).
            float Afr[32];
            #pragma unroll
            for (int kb = 0; kb < 8; ++kb) {
                Afr[kb*4+0] = act[p][g][kb*8 + tig];
                Afr[kb*4+1] = act[p][g+8][kb*8 + tig];
                Afr[kb*4+2] = act[p][g][kb*8 + tig + 4];
                Afr[kb*4+3] = act[p][g+8][kb*8 + tig + 4];
            }
            __syncthreads();   // all A reads done before epilogue writes

            float acc[16];
            #pragma unroll
            for (int i = 0; i < 16; ++i) acc[i] = 0.f;
            #pragma unroll
            for (int kb = 0; kb < 8; ++kb)
                #pragma unroll
                for (int nb = 0; nb < 4; ++nb)
                    mma8(acc + nb*4, Afr + kb*4, Bf[kb*4+nb]);

            const float* bl = (l == 0) ? bp0 : (l == 1) ? bp1
                            : (l == 2) ? bp2 : bpo;
            float2 bias[4];
            #pragma unroll
            for (int nb = 0; nb < 4; ++nb)
                bias[nb] = *(const float2*)(bl + f*64 + 32*h + nb*8 + 2*tig);

            if (l < 3) {
                #pragma unroll
                for (int nb = 0; nb < 4; ++nb) {
                    const int c = 32*h + nb*8 + 2*tig;
                    float v0 = fmaxf(acc[nb*4+0] + bias[nb].x, 0.f);
                    float v1 = fmaxf(acc[nb*4+1] + bias[nb].y, 0.f);
                    float v2 = fmaxf(acc[nb*4+2] + bias[nb].x, 0.f);
                    float v3 = fmaxf(acc[nb*4+3] + bias[nb].y, 0.f);
                    *(float2*)&act[p][g][c]   = make_float2(v0, v1);
                    *(float2*)&act[p][g+8][c] = make_float2(v2, v3);
                }
                __syncthreads();
            } else {
                float zn[16];
                #pragma unroll
                for (int nb = 0; nb < 4; ++nb) {
                    const int c = 32*h + nb*8 + 2*tig;
                    float2 z0 = *(float2*)&zbuf[p][g][c];
                    float2 z1 = *(float2*)&zbuf[p][g+8][c];
                    zn[nb*4+0] = z0.x - (acc[nb*4+0] + bias[nb].x);
                    zn[nb*4+1] = z0.y - (acc[nb*4+1] + bias[nb].y);
                    zn[nb*4+2] = z1.x - (acc[nb*4+2] + bias[nb].x);
                    zn[nb*4+3] = z1.y - (acc[nb*4+3] + bias[nb].y);
                }
                if (fi == 0) {
                    __syncthreads();   // all zbuf reads done
                    #pragma unroll
                    for (int nb = 0; nb < 4; ++nb) {
                        const int c  = 32*h + nb*8 + 2*tig;
                        const int rc = 62 - c;          // reversed float2 base
                        float2 w0 = make_float2(zn[nb*4+1], zn[nb*4+0]);
                        float2 w1 = make_float2(zn[nb*4+3], zn[nb*4+2]);
                        *(float2*)&act[p][g][rc]    = w0;
                        *(float2*)&act[p][g+8][rc]  = w1;
                        *(float2*)&zbuf[p][g][rc]   = w0;
                        *(float2*)&zbuf[p][g+8][rc] = w1;
                    }
                    __syncthreads();
                } else {
                    const int r0 = rowbase + g, r1 = r0 + 8;
                    #pragma unroll
                    for (int nb = 0; nb < 4; ++nb) {
                        const int c = 32*h + nb*8 + 2*tig;
                        if (r0 < B)
                            *(float2*)(out + (size_t)r0*64 + c) =
                                make_float2(zn[nb*4+0], zn[nb*4+1]);
                        if (r1 < B)
                            *(float2*)(out + (size_t)r1*64 + c) =
                                make_float2(zn[nb*4+2], zn[nb*4+3]);
                    }
                }
            }
        }
    }
}

extern "C" void kernel_launch(void* const* d_in, const int* in_sizes, int n_in,
                              void* d_out, int out_size) {
    const float* zm = (const float*)d_in[0];
    const float* lv = (const float*)d_in[1];
    const float* ep = (const float*)d_in[2];
    const float* W0 = (const float*)d_in[3];
    const float* b0 = (const float*)d_in[4];
    const float* W1 = (const float*)d_in[5];
    const float* b1 = (const float*)d_in[6];
    const float* W2 = (const float*)d_in[7];
    const float* b2 = (const float*)d_in[8];
    const float* Wo = (const float*)d_in[9];
    const float* bo = (const float*)d_in[10];

    int B = in_sizes[0] / 64;

    prep_kernel<<<64, 256>>>(W0, W1, W2, Wo);
    int grid = (B + 31) / 32;
    iaf_main<<<grid, 128>>>(zm, lv, ep, b0, b1, b2, bo, (float*)d_out, B);
}

// round 8
// speedup vs baseline: 3.9494x; 1.2612x over previous
#include <cuda_runtime.h>
#include <math.h>
#include <stdint.h>

// IAF, 2 MADE flows, B=4096, D=H=64.
// Identity (verified R1/R4-R7): the reference forward scan is the exact inverse
// of z -> z - shift(z), so density = -0.5*D*log(2pi) - 0.5*sum(lv)
// - 0.5*sum(eps^2); only the inverse pass (8 masked [Bx64]@[64x64] GEMMs) runs.
// R8: 8 warps/block = 2 tiles x 4 column-quarters; next-layer B-fragments
// prefetched into registers during MMAs; biases staged in smem; ping-pong
// activation buffers (1 barrier/layer); layers fully unrolled.

#define C_DENS (-58.81206612509905f)
#define AST 68

__device__ float2 g_wfrag[8 * 64 * 32];   // 128 KB: [mat][kb*8+nb][lane]

static __device__ __forceinline__ float tf32r(float x) {
    uint32_t y;
    asm("cvt.rna.tf32.f32 %0, %1;" : "=r"(y) : "f"(x));
    return __uint_as_float(y);
}

static __device__ __forceinline__ void mma8(float* d, const float* a, float2 b) {
    asm volatile(
        "mma.sync.aligned.m16n8k8.row.col.f32.tf32.tf32.f32 "
        "{%0,%1,%2,%3}, {%4,%5,%6,%7}, {%8,%9}, {%0,%1,%2,%3};"
        : "+f"(d[0]), "+f"(d[1]), "+f"(d[2]), "+f"(d[3])
        : "r"(__float_as_uint(a[0])), "r"(__float_as_uint(a[1])),
          "r"(__float_as_uint(a[2])), "r"(__float_as_uint(a[3])),
          "r"(__float_as_uint(b.x)), "r"(__float_as_uint(b.y)));
}

// ---- Prep: mask + tf32-round + tile weights into B-fragment layout.
__global__ void prep_kernel(const float* __restrict__ W0,
                            const float* __restrict__ W1,
                            const float* __restrict__ W2,
                            const float* __restrict__ Wo) {
    int idx  = blockIdx.x * 256 + threadIdx.x;    // 0..16383
    int lane = idx & 31;
    int frag = (idx >> 5) & 63;
    int mat  = idx >> 11;                          // f*4 + l
    int f = mat >> 2, l = mat & 3;
    int kb = frag >> 3, nb = frag & 7;
    int g = lane >> 2, tig = lane & 3;
    int n = nb * 8 + g;
    const float* src = (l == 0) ? W0 : (l == 1) ? W1 : (l == 2) ? W2 : Wo;
    src += f * 4096;
    int k0 = kb * 8 + tig, k1 = k0 + 4;
    bool m0, m1;
    if (l == 0)      { m0 = (k0 <= n % 63);        m1 = (k1 <= n % 63); }
    else if (l == 3) { m0 = ((k0 % 63) < n);       m1 = ((k1 % 63) < n); }
    else             { m0 = ((k0 % 63) <= n % 63); m1 = ((k1 % 63) <= n % 63); }
    float b0v = m0 ? tf32r(src[k0 * 64 + n]) : 0.0f;
    float b1v = m1 ? tf32r(src[k1 * 64 + n]) : 0.0f;
    g_wfrag[idx] = make_float2(b0v, b1v);
}

__global__ __launch_bounds__(256, 1)
void iaf_main(const float* __restrict__ zm, const float* __restrict__ lv,
              const float* __restrict__ ep,
              const float* __restrict__ bp0, const float* __restrict__ bp1,
              const float* __restrict__ bp2, const float* __restrict__ bpo,
              float* __restrict__ out, int B)
{
    __shared__ float act[2][2][16][AST];   // [buf][tile][row][col]
    __shared__ float zbuf[2][16][AST];     // exact-fp32 z
    __shared__ float bsm[8][64];           // biases, [f*4+l][col]
    const int t = threadIdx.x;

    // ---- Init: biases to smem; z0 = zm + exp(0.5*lv)*eps; density.
    for (int idx = t; idx < 512; idx += 256) {
        int mat = idx >> 6, j = idx & 63;
        int f = mat >> 2, l = mat & 3;
        const float* bl = (l == 0) ? bp0 : (l == 1) ? bp1 : (l == 2) ? bp2 : bpo;
        bsm[mat][j] = bl[f * 64 + j];
    }
    {
        int r = t >> 3, seg = t & 7;           // 32 rows x 8 col-segments
        int pi = r >> 4, ri = r & 15;
        int gr = blockIdx.x * 32 + r;
        bool v = gr < B;
        float slv = 0.f, se2 = 0.f;
        #pragma unroll
        for (int q = 0; q < 2; ++q) {
            int col = seg * 8 + q * 4;
            const size_t go = (size_t)gr * 64 + col;
            float4 a = v ? *(const float4*)(zm + go) : make_float4(0,0,0,0);
            float4 b = v ? *(const float4*)(lv + go) : make_float4(0,0,0,0);
            float4 c = v ? *(const float4*)(ep + go) : make_float4(0,0,0,0);
            float4 z4;
            z4.x = a.x + __expf(0.5f * b.x) * c.x;
            z4.y = a.y + __expf(0.5f * b.y) * c.y;
            z4.z = a.z + __expf(0.5f * b.z) * c.z;
            z4.w = a.w + __expf(0.5f * b.w) * c.w;
            *(float4*)&act[0][pi][ri][col] = z4;
            *(float4*)&zbuf[pi][ri][col]   = z4;
            slv += b.x + b.y + b.z + b.w;
            se2 += c.x*c.x + c.y*c.y + c.z*c.z + c.w*c.w;
        }
        #pragma unroll
        for (int m = 1; m <= 4; m <<= 1) {
            slv += __shfl_xor_sync(0xffffffffu, slv, m);
            se2 += __shfl_xor_sync(0xffffffffu, se2, m);
        }
        if (seg == 0 && v)
            out[(size_t)B * 64 + gr] = C_DENS - 0.5f * slv - 0.5f * se2;
    }

    const int lane = t & 31, wid = t >> 5;
    const int p = wid >> 2, h = wid & 3;       // tile, column quarter (16 cols)
    const int g = lane >> 2, tig = lane & 3;
    const int rowbase = blockIdx.x * 32 + p * 16;

    // Prefetch layer 0 B-fragments (mat order: 4,5,6,7,0,1,2,3).
    float2 Bcur[16], Bnxt[16];
    {
        const float2* wf = g_wfrag + 4 * 2048 + 2 * h * 32 + lane;
        #pragma unroll
        for (int kb = 0; kb < 8; ++kb) {
            Bcur[kb*2+0] = wf[kb * 256];
            Bcur[kb*2+1] = wf[kb * 256 + 32];
        }
    }
    __syncthreads();

    // ---- 8 chained layers, fully unrolled.
    #pragma unroll
    for (int li = 0; li < 8; ++li) {
        const int mat = (li < 4) ? (4 + li) : (li - 4);
        const int l   = mat & 3;
        const int rd  = li & 1, wr = (li + 1) & 1;

        // Prefetch next layer's B-fragments (overlaps this layer's MMAs).
        if (li < 7) {
            const int nmat = (li < 3) ? (5 + li) : (li - 3);
            const float2* wf = g_wfrag + nmat * 2048 + 2 * h * 32 + lane;
            #pragma unroll
            for (int kb = 0; kb < 8; ++kb) {
                Bnxt[kb*2+0] = wf[kb * 256];
                Bnxt[kb*2+1] = wf[kb * 256 + 32];
            }
        }

        // A-fragments (conflict-free LDS: bank = 4g + tig).
        float Afr[32];
        #pragma unroll
        for (int kb = 0; kb < 8; ++kb) {
            Afr[kb*4+0] = act[rd][p][g][kb*8 + tig];
            Afr[kb*4+1] = act[rd][p][g+8][kb*8 + tig];
            Afr[kb*4+2] = act[rd][p][g][kb*8 + tig + 4];
            Afr[kb*4+3] = act[rd][p][g+8][kb*8 + tig + 4];
        }

        float acc[8];
        #pragma unroll
        for (int i = 0; i < 8; ++i) acc[i] = 0.f;
        #pragma unroll
        for (int kb = 0; kb < 8; ++kb) {
            mma8(acc + 0, Afr + kb*4, Bcur[kb*2+0]);
            mma8(acc + 4, Afr + kb*4, Bcur[kb*2+1]);
        }

        float2 bias[2];
        bias[0] = *(const float2*)&bsm[mat][16*h + 2*tig];
        bias[1] = *(const float2*)&bsm[mat][16*h + 8 + 2*tig];

        if (l < 3) {
            #pragma unroll
            for (int j = 0; j < 2; ++j) {
                const int c = 16*h + j*8 + 2*tig;
                float v0 = fmaxf(acc[j*4+0] + bias[j].x, 0.f);
                float v1 = fmaxf(acc[j*4+1] + bias[j].y, 0.f);
                float v2 = fmaxf(acc[j*4+2] + bias[j].x, 0.f);
                float v3 = fmaxf(acc[j*4+3] + bias[j].y, 0.f);
                *(float2*)&act[wr][p][g][c]   = make_float2(v0, v1);
                *(float2*)&act[wr][p][g+8][c] = make_float2(v2, v3);
            }
            __syncthreads();
        } else {
            float zn[8];
            #pragma unroll
            for (int j = 0; j < 2; ++j) {
                const int c = 16*h + j*8 + 2*tig;
                float2 z0 = *(float2*)&zbuf[p][g][c];
                float2 z1 = *(float2*)&zbuf[p][g+8][c];
                zn[j*4+0] = z0.x - (acc[j*4+0] + bias[j].x);
                zn[j*4+1] = z0.y - (acc[j*4+1] + bias[j].y);
                zn[j*4+2] = z1.x - (acc[j*4+2] + bias[j].x);
                zn[j*4+3] = z1.y - (acc[j*4+3] + bias[j].y);
            }
            if (li == 3) {
                __syncthreads();   // zbuf reads done before reversed writes
                #pragma unroll
                for (int j = 0; j < 2; ++j) {
                    const int c  = 16*h + j*8 + 2*tig;
                    const int rc = 62 - c;
                    float2 w0 = make_float2(zn[j*4+1], zn[j*4+0]);
                    float2 w1 = make_float2(zn[j*4+3], zn[j*4+2]);
                    *(float2*)&act[wr][p][g][rc]   = w0;
                    *(float2*)&act[wr][p][g+8][rc] = w1;
                    *(float2*)&zbuf[p][g][rc]      = w0;
                    *(float2*)&zbuf[p][g+8][rc]    = w1;
                }
                __syncthreads();
            } else {
                const int r0 = rowbase + g, r1 = r0 + 8;
                #pragma unroll
                for (int j = 0; j < 2; ++j) {
                    const int c = 16*h + j*8 + 2*tig;
                    if (r0 < B)
                        *(float2*)(out + (size_t)r0*64 + c) =
                            make_float2(zn[j*4+0], zn[j*4+1]);
                    if (r1 < B)
                        *(float2*)(out + (size_t)r1*64 + c) =
                            make_float2(zn[j*4+2], zn[j*4+3]);
                }
            }
        }

        // Rotate prefetch buffer (register renames under full unroll).
        #pragma unroll
        for (int i = 0; i < 16; ++i) Bcur[i] = Bnxt[i];
    }
}

extern "C" void kernel_launch(void* const* d_in, const int* in_sizes, int n_in,
                              void* d_out, int out_size) {
    const float* zm = (const float*)d_in[0];
    const float* lv = (const float*)d_in[1];
    const float* ep = (const float*)d_in[2];
    const float* W0 = (const float*)d_in[3];
    const float* b0 = (const float*)d_in[4];
    const float* W1 = (const float*)d_in[5];
    const float* b1 = (const float*)d_in[6];
    const float* W2 = (const float*)d_in[7];
    const float* b2 = (const float*)d_in[8];
    const float* Wo = (const float*)d_in[9];
    const float* bo = (const float*)d_in[10];

    int B = in_sizes[0] / 64;

    prep_kernel<<<64, 256>>>(W0, W1, W2, Wo);
    int grid = (B + 31) / 32;
    iaf_main<<<grid, 256>>>(zm, lv, ep, b0, b1, b2, bo, (float*)d_out, B);
}